// round 12
// baseline (speedup 1.0000x reference)
#include <cuda_runtime.h>
#include <math.h>

// ---------------- problem constants ----------------
#define NTOK   131072          // H*W*B = 64*64*32
#define CDIM   512
#define NB     2048            // Nb axis = ws*ws*B
#define BATCH  32
#define SHIFTV 4

// ---------------- scratch (device globals; no allocs allowed) ----------------
__device__ float g_xw  [(size_t)NTOK * CDIM];        // LN1 + shifted window partition
__device__ float g_qkv [(size_t)NTOK * 3 * CDIM];    // qkv activations
__device__ float g_ctx [(size_t)NTOK * CDIM];        // attention context
__device__ float g_attn[(size_t)NTOK * CDIM];        // proj out + residual (window order)
__device__ float g_hs  [(size_t)NTOK * CDIM];        // hidden + LN2(hidden)  (fc2 residual)
__device__ float g_zln [(size_t)NTOK * CDIM];        // LN2(hidden)           (fc1 input)
__device__ float g_act1[(size_t)NTOK * 4 * CDIM];    // gelu(fc1)

// ---------------- helpers ----------------
__device__ __forceinline__ float warp_sum(float v) {
#pragma unroll
    for (int o = 16; o; o >>= 1) v += __shfl_xor_sync(0xffffffffu, v, o);
    return v;
}

__device__ __forceinline__ unsigned f2tf32(float x) {
    unsigned r;
    asm("cvt.rna.tf32.f32 %0, %1;" : "=r"(r) : "f"(x));
    return r;
}

__device__ __forceinline__ void mma_tf32(float (&d)[4], const unsigned (&a)[4], const unsigned (&b)[2]) {
    asm volatile(
        "mma.sync.aligned.m16n8k8.row.col.f32.tf32.tf32.f32 "
        "{%0,%1,%2,%3}, {%4,%5,%6,%7}, {%8,%9}, {%0,%1,%2,%3};"
        : "+f"(d[0]), "+f"(d[1]), "+f"(d[2]), "+f"(d[3])
        : "r"(a[0]), "r"(a[1]), "r"(a[2]), "r"(a[3]), "r"(b[0]), "r"(b[1]));
}

__device__ __forceinline__ float gelu_exact(float x) {
    return 0.5f * x * (1.0f + erff(x * 0.70710678118654752f));
}

// ---------------- K1: LN1 + roll(-4,-4) + window partition ----------------
__global__ void ln1_partition_kernel(const float* __restrict__ x,
                                     const float* __restrict__ g,
                                     const float* __restrict__ b,
                                     float* __restrict__ y)
{
    int warp = (blockIdx.x * blockDim.x + threadIdx.x) >> 5;
    int lane = threadIdx.x & 31;
    int r = warp;
    int win = r >> 11, n = r & 2047;
    int p = n >> 5, bb = n & 31;
    int hs = ((win >> 3) * 8 + (p >> 3) + SHIFTV) & 63;
    int ws2 = ((win & 7) * 8 + (p & 7) + SHIFTV) & 63;
    size_t src = (((size_t)(hs * 64 + ws2)) * BATCH + bb) * CDIM;

    float4 v[4];
#pragma unroll
    for (int q = 0; q < 4; q++)
        v[q] = *(const float4*)(x + src + (size_t)(q * 32 + lane) * 4);

    float s = 0.f;
#pragma unroll
    for (int q = 0; q < 4; q++) s += v[q].x + v[q].y + v[q].z + v[q].w;
    s = warp_sum(s);
    float mu = s * (1.0f / 512.0f);

    float vs = 0.f;
#pragma unroll
    for (int q = 0; q < 4; q++) {
        float a0 = v[q].x - mu, a1 = v[q].y - mu, a2 = v[q].z - mu, a3 = v[q].w - mu;
        vs += a0 * a0 + a1 * a1 + a2 * a2 + a3 * a3;
    }
    vs = warp_sum(vs);
    float rstd = rsqrtf(vs * (1.0f / 512.0f) + 1e-5f);

    size_t dst = (size_t)r * CDIM;
#pragma unroll
    for (int q = 0; q < 4; q++) {
        int c0 = (q * 32 + lane) * 4;
        float4 gv = __ldg((const float4*)(g + c0));
        float4 bv = __ldg((const float4*)(b + c0));
        float4 o;
        o.x = (v[q].x - mu) * rstd * gv.x + bv.x;
        o.y = (v[q].y - mu) * rstd * gv.y + bv.y;
        o.z = (v[q].z - mu) * rstd * gv.z + bv.z;
        o.w = (v[q].w - mu) * rstd * gv.w + bv.w;
        *(float4*)(y + dst + c0) = o;
    }
}

// ---------------- K5: window reverse + unshift + residual + LN2 ----------------
// writes: zln = LN2(hidden)            (FC1 input)
//         hs  = hidden + LN2(hidden)   (FC2 epilogue residual)
__global__ void reverse_ln2_kernel(const float* __restrict__ x0,
                                   const float* __restrict__ attn,
                                   const float* __restrict__ g,
                                   const float* __restrict__ b,
                                   float* __restrict__ hs,
                                   float* __restrict__ zln)
{
    int warp = (blockIdx.x * blockDim.x + threadIdx.x) >> 5;
    int lane = threadIdx.x & 31;
    int t = warp;
    int simg = t >> 5, bb = t & 31;
    int h = simg >> 6, w = simg & 63;
    int hp = (h + 64 - SHIFTV) & 63, wp = (w + 64 - SHIFTV) & 63;
    size_t r = ((size_t)((hp >> 3) * 8 + (wp >> 3)) * NB +
                (size_t)(((hp & 7) * 8 + (wp & 7)) * 32 + bb)) * CDIM;
    size_t d0 = (size_t)t * CDIM;

    float4 v[4];
#pragma unroll
    for (int q = 0; q < 4; q++) {
        int c0 = (q * 32 + lane) * 4;
        float4 a = *(const float4*)(x0 + d0 + c0);
        float4 c = *(const float4*)(attn + r + c0);
        v[q].x = a.x + c.x; v[q].y = a.y + c.y; v[q].z = a.z + c.z; v[q].w = a.w + c.w;
    }

    float s = 0.f;
#pragma unroll
    for (int q = 0; q < 4; q++) s += v[q].x + v[q].y + v[q].z + v[q].w;
    s = warp_sum(s);
    float mu = s * (1.0f / 512.0f);
    float vsum = 0.f;
#pragma unroll
    for (int q = 0; q < 4; q++) {
        float a0 = v[q].x - mu, a1 = v[q].y - mu, a2 = v[q].z - mu, a3 = v[q].w - mu;
        vsum += a0 * a0 + a1 * a1 + a2 * a2 + a3 * a3;
    }
    vsum = warp_sum(vsum);
    float rstd = rsqrtf(vsum * (1.0f / 512.0f) + 1e-5f);

#pragma unroll
    for (int q = 0; q < 4; q++) {
        int c0 = (q * 32 + lane) * 4;
        float4 gv = __ldg((const float4*)(g + c0));
        float4 bv = __ldg((const float4*)(b + c0));
        float4 o;
        o.x = (v[q].x - mu) * rstd * gv.x + bv.x;
        o.y = (v[q].y - mu) * rstd * gv.y + bv.y;
        o.z = (v[q].z - mu) * rstd * gv.z + bv.z;
        o.w = (v[q].w - mu) * rstd * gv.w + bv.w;
        *(float4*)(zln + d0 + c0) = o;
        float4 hv;
        hv.x = v[q].x + o.x; hv.y = v[q].y + o.y;
        hv.z = v[q].z + o.z; hv.w = v[q].w + o.w;
        *(float4*)(hs + d0 + c0) = hv;
    }
}

// ---------------- attention: one block per (n, h); 64 threads, thread = row s ----------------
__global__ __launch_bounds__(64)
void attn_kernel(const float* __restrict__ qkv, float* __restrict__ ctx)
{
    __shared__ float ksm[64][36];
    __shared__ float vsm[64][36];
    __shared__ int   rsm[64];       // region id per sequence position (mask)
    int n = blockIdx.x, hh = blockIdx.y, s = threadIdx.x;
    size_t base = ((size_t)s * NB + n) * 1536 + hh * 96;

    float4 q[8];
#pragma unroll
    for (int d = 0; d < 8; d++) q[d] = *(const float4*)(qkv + base + d * 4);
#pragma unroll
    for (int d = 0; d < 8; d++) {
        *(float4*)&ksm[s][d * 4] = *(const float4*)(qkv + base + 32 + d * 4);
        *(float4*)&vsm[s][d * 4] = *(const float4*)(qkv + base + 64 + d * 4);
    }

    // mask row for this n: mask[n % 64]; (s,t) index the sequence axis.
    // region id computed ONCE per position (by thread s for position s),
    // consumed via broadcast LDS in the score loop.
    {
        int wm = n & 63;
        int hr = (wm >> 3) * 8 + (s >> 3);
        int wr = (wm & 7) * 8 + (s & 7);
        int a = (hr < 56) ? 0 : (hr < 60 ? 1 : 2);
        int c = (wr < 56) ? 0 : (wr < 60 ? 1 : 2);
        rsm[s] = a * 3 + c;
    }
    __syncthreads();

    int rs = rsm[s];

    float sc[64];
#pragma unroll
    for (int t = 0; t < 64; t++) {
        float dot = 0.f;
#pragma unroll
        for (int d = 0; d < 8; d++) {
            float4 kv = *(const float4*)&ksm[t][d * 4];
            dot += q[d].x * kv.x + q[d].y * kv.y + q[d].z * kv.z + q[d].w * kv.w;
        }
        sc[t] = (rsm[t] != rs) ? -10000.0f : dot * 0.17677669529663687f;
    }

    float mx = -1e30f;
#pragma unroll
    for (int t = 0; t < 64; t++) mx = fmaxf(mx, sc[t]);
    float sum = 0.f;
#pragma unroll
    for (int t = 0; t < 64; t++) { sc[t] = expf(sc[t] - mx); sum += sc[t]; }
    float inv = 1.0f / sum;

    float acc[32];
#pragma unroll
    for (int d = 0; d < 32; d++) acc[d] = 0.f;
#pragma unroll
    for (int t = 0; t < 64; t++) {
        float pt = sc[t];
#pragma unroll
        for (int d = 0; d < 8; d++) {
            float4 vv = *(const float4*)&vsm[t][d * 4];
            acc[d * 4 + 0] += pt * vv.x;
            acc[d * 4 + 1] += pt * vv.y;
            acc[d * 4 + 2] += pt * vv.z;
            acc[d * 4 + 3] += pt * vv.w;
        }
    }
    size_t ob = ((size_t)s * NB + n) * CDIM + hh * 32;
#pragma unroll
    for (int d = 0; d < 8; d++)
        *(float4*)(ctx + ob + d * 4) = make_float4(acc[d*4]*inv, acc[d*4+1]*inv,
                                                   acc[d*4+2]*inv, acc[d*4+3]*inv);
}

// ---------------- tf32 mma GEMM, double-buffered + fragment-packed smem ----
// C[M,N] = A[M,K] @ B[K,N] (+ epilogue)
// EPI 0: +bias   1: +bias +R1   2: gelu(+bias)
//
// Packed A layout (per 128x32 tile, 4096 words):
//   word((row,c)) = ((g16*4+ks)*32 + gid*4 + tig)*4 + chalf*2 + rhalf
//   g16=row>>4, rhalf=(row>>3)&1, gid=row&7, ks=c>>3, tig=c&3, chalf=(c>>2)&1
//   -> per-thread a-frag {a0,a1,a2,a3} = one uint4 load, conflict-free.
// Packed B layout (per 32x128 tile, 4096 words), XOR-swizzled columns:
//   word((r,c)) = ((ks*4+tig)*128 + (c ^ (tig*8)))*2 + rhalf
//   ks=r>>3, tig=r&3, rhalf=(r>>2)&1
//   -> per-thread b-frag pair {b0,b1} = one uint2 load, 2-phase (floor).
#define TILE_WORDS 4096
#define GEMM_SMEM (4 * TILE_WORDS * 4)   // 65536 B (A0,A1,B0,B1)

template<int EPI>
__global__ __launch_bounds__(256)
void gemm_tf32(const float* __restrict__ A, const float* __restrict__ B,
               const float* __restrict__ bias, float* __restrict__ C,
               const float* __restrict__ R1,
               int M, int N, int K)
{
    extern __shared__ unsigned smem[];
    unsigned* Apk = smem;                       // [2][TILE_WORDS]
    unsigned* Bpk = smem + 2 * TILE_WORDS;      // [2][TILE_WORDS]

    int tid = threadIdx.x;
    int lane = tid & 31, wid = tid >> 5;
    int wm = wid >> 1, wn = wid & 1;            // 4x2 warp grid: 32 rows x 64 cols each
    int gid = lane >> 2, tig = lane & 3;

    size_t bm0 = (size_t)blockIdx.y * 128;
    int bn0 = blockIdx.x * 128;

    // global staging coordinates
    const int a_row = tid >> 3;                 // + 32*l
    const int a_cc  = (tid & 7) * 4;            // k-local col base
    const int b_row = tid >> 5;                 // + 8*l   (k-local row)
    const int b_cc  = (tid & 31) * 4;           // col base

    // packed-store word bases (constant across k-tiles)
    int wbA[4], wbB[4];
#pragma unroll
    for (int l = 0; l < 4; l++) {
        int row = a_row + 32 * l;
        wbA[l] = (((row >> 4) * 4 + (a_cc >> 3)) * 32 + (row & 7) * 4) * 4
               + ((a_cc >> 2) & 1) * 2 + ((row >> 3) & 1);
    }
#pragma unroll
    for (int l = 0; l < 4; l++) {
        int r = b_row + 8 * l;
        wbB[l] = (((r >> 3) * 4 + (r & 3)) * 128 + (b_cc ^ ((r & 3) * 8))) * 2
               + ((r >> 2) & 1);
    }

    float acc[2][8][4];
#pragma unroll
    for (int mt = 0; mt < 2; mt++)
#pragma unroll
        for (int nt = 0; nt < 8; nt++)
#pragma unroll
            for (int i = 0; i < 4; i++) acc[mt][nt][i] = 0.f;

    const int NT = K >> 5;

    // ---- prologue: tile 0 into buffer 0 ----
    {
        float4 pa[4], pb[4];
#pragma unroll
        for (int l = 0; l < 4; l++)
            pa[l] = __ldg((const float4*)(A + (bm0 + a_row + 32 * l) * (size_t)K + a_cc));
#pragma unroll
        for (int l = 0; l < 4; l++)
            pb[l] = __ldg((const float4*)(B + (size_t)(b_row + 8 * l) * N + bn0 + b_cc));
#pragma unroll
        for (int l = 0; l < 4; l++) {
            unsigned* d = Apk + wbA[l];
            d[0] = f2tf32(pa[l].x); d[4]  = f2tf32(pa[l].y);
            d[8] = f2tf32(pa[l].z); d[12] = f2tf32(pa[l].w);
        }
#pragma unroll
        for (int l = 0; l < 4; l++) {
            unsigned* d = Bpk + wbB[l];
            d[0] = f2tf32(pb[l].x); d[2] = f2tf32(pb[l].y);
            d[4] = f2tf32(pb[l].z); d[6] = f2tf32(pb[l].w);
        }
    }
    __syncthreads();

    for (int kt = 0; kt < NT; kt++) {
        const unsigned* Ac = Apk + (kt & 1) * TILE_WORDS;
        const unsigned* Bc = Bpk + (kt & 1) * TILE_WORDS;
        bool has = (kt + 1 < NT);

        // ---- issue prefetch LDGs for tile kt+1 (latency hidden behind MMAs) ----
        float4 pa[4], pb[4];
        if (has) {
            int k0 = (kt + 1) << 5;
#pragma unroll
            for (int l = 0; l < 4; l++)
                pa[l] = __ldg((const float4*)(A + (bm0 + a_row + 32 * l) * (size_t)K + k0 + a_cc));
#pragma unroll
            for (int l = 0; l < 4; l++)
                pb[l] = __ldg((const float4*)(B + (size_t)(k0 + b_row + 8 * l) * N + bn0 + b_cc));
        }

        // ---- compute current tile ----
#pragma unroll
        for (int ks = 0; ks < 4; ks++) {
            unsigned a[2][4], b[8][2];
#pragma unroll
            for (int mt = 0; mt < 2; mt++) {
                int g16 = wm * 2 + mt;
                uint4 av = *(const uint4*)(Ac + ((g16 * 4 + ks) * 32 + gid * 4 + tig) * 4);
                a[mt][0] = av.x; a[mt][1] = av.y; a[mt][2] = av.z; a[mt][3] = av.w;
            }
#pragma unroll
            for (int nt = 0; nt < 8; nt++) {
                int c0 = wn * 64 + nt * 8 + gid;
                int c0s = c0 ^ (tig * 8);
                uint2 bv = *(const uint2*)(Bc + ((ks * 4 + tig) * 128 + c0s) * 2);
                b[nt][0] = bv.x; b[nt][1] = bv.y;
            }
#pragma unroll
            for (int mt = 0; mt < 2; mt++)
#pragma unroll
                for (int nt = 0; nt < 8; nt++)
                    mma_tf32(acc[mt][nt], a[mt], b[nt]);
        }

        // ---- commit prefetched tile into the other buffer ----
        if (has) {
            unsigned* An = Apk + ((kt + 1) & 1) * TILE_WORDS;
            unsigned* Bn = Bpk + ((kt + 1) & 1) * TILE_WORDS;
#pragma unroll
            for (int l = 0; l < 4; l++) {
                unsigned* d = An + wbA[l];
                d[0] = f2tf32(pa[l].x); d[4]  = f2tf32(pa[l].y);
                d[8] = f2tf32(pa[l].z); d[12] = f2tf32(pa[l].w);
            }
#pragma unroll
            for (int l = 0; l < 4; l++) {
                unsigned* d = Bn + wbB[l];
                d[0] = f2tf32(pb[l].x); d[2] = f2tf32(pb[l].y);
                d[4] = f2tf32(pb[l].z); d[6] = f2tf32(pb[l].w);
            }
        }
        __syncthreads();
    }

    // ---- epilogue ----
#pragma unroll
    for (int mt = 0; mt < 2; mt++) {
#pragma unroll
        for (int half = 0; half < 2; half++) {
            size_t row = bm0 + wm * 32 + mt * 16 + gid + half * 8;
#pragma unroll
            for (int nt = 0; nt < 8; nt++) {
                int col = bn0 + wn * 64 + nt * 8 + tig * 2;
                float2 bv = __ldg((const float2*)(bias + col));
                float v0 = acc[mt][nt][half * 2 + 0] + bv.x;
                float v1 = acc[mt][nt][half * 2 + 1] + bv.y;
                size_t idx = row * (size_t)N + col;
                if (EPI == 1) {
                    float2 r1 = *(const float2*)(R1 + idx);
                    v0 += r1.x; v1 += r1.y;
                }
                if (EPI == 2) { v0 = gelu_exact(v0); v1 = gelu_exact(v1); }
                *(float2*)(C + idx) = make_float2(v0, v1);
            }
        }
    }
}

// ---------------- launch ----------------
extern "C" void kernel_launch(void* const* d_in, const int* in_sizes, int n_in,
                              void* d_out, int out_size)
{
    const float* hid    = (const float*)d_in[0];
    const float* ln1_g  = (const float*)d_in[1];
    const float* ln1_b  = (const float*)d_in[2];
    const float* w_qkv  = (const float*)d_in[3];
    const float* b_qkv  = (const float*)d_in[4];
    const float* w_proj = (const float*)d_in[5];
    const float* b_proj = (const float*)d_in[6];
    const float* ln2_g  = (const float*)d_in[7];
    const float* ln2_b  = (const float*)d_in[8];
    const float* w_fc1  = (const float*)d_in[9];
    const float* b_fc1  = (const float*)d_in[10];
    const float* w_fc2  = (const float*)d_in[11];
    const float* b_fc2  = (const float*)d_in[12];
    float* out = (float*)d_out;

    float *xw, *qkv, *ctx, *attn, *hs, *zln, *act1;
    cudaGetSymbolAddress((void**)&xw,   g_xw);
    cudaGetSymbolAddress((void**)&qkv,  g_qkv);
    cudaGetSymbolAddress((void**)&ctx,  g_ctx);
    cudaGetSymbolAddress((void**)&attn, g_attn);
    cudaGetSymbolAddress((void**)&hs,   g_hs);
    cudaGetSymbolAddress((void**)&zln,  g_zln);
    cudaGetSymbolAddress((void**)&act1, g_act1);

    // allow 64KB dynamic smem on the GEMM instantiations (attribute set, not an alloc)
    cudaFuncSetAttribute(gemm_tf32<0>, cudaFuncAttributeMaxDynamicSharedMemorySize, GEMM_SMEM);
    cudaFuncSetAttribute(gemm_tf32<1>, cudaFuncAttributeMaxDynamicSharedMemorySize, GEMM_SMEM);
    cudaFuncSetAttribute(gemm_tf32<2>, cudaFuncAttributeMaxDynamicSharedMemorySize, GEMM_SMEM);

    // 1) LN1 + shift + partition
    ln1_partition_kernel<<<NTOK / 8, 256>>>(hid, ln1_g, ln1_b, xw);
    // 2) QKV GEMM [131072,512]x[512,1536]
    gemm_tf32<0><<<dim3(1536 / 128, NTOK / 128), 256, GEMM_SMEM>>>(xw, w_qkv, b_qkv, qkv,
                                                                   nullptr, NTOK, 1536, 512);
    // 3) windowed attention
    attn_kernel<<<dim3(NB, 16), 64>>>(qkv, ctx);
    // 4) proj GEMM + residual(xw)
    gemm_tf32<1><<<dim3(512 / 128, NTOK / 128), 256, GEMM_SMEM>>>(ctx, w_proj, b_proj, attn,
                                                                  xw, NTOK, 512, 512);
    // 5) window reverse + unshift + residual + LN2  (hs = hidden + zln)
    reverse_ln2_kernel<<<NTOK / 8, 256>>>(hid, attn, ln2_g, ln2_b, hs, zln);
    // 6) FC1 + gelu
    gemm_tf32<2><<<dim3(2048 / 128, NTOK / 128), 256, GEMM_SMEM>>>(zln, w_fc1, b_fc1, act1,
                                                                   nullptr, NTOK, 2048, 512);
    // 7) FC2 + bias + (hidden + zln)  -> final output
    gemm_tf32<1><<<dim3(512 / 128, NTOK / 128), 256, GEMM_SMEM>>>(act1, w_fc2, b_fc2, out,
                                                                  hs, NTOK, 512, 2048);
}

// round 15
// speedup vs baseline: 1.7594x; 1.7594x over previous
#include <cuda_runtime.h>
#include <math.h>

// ---------------- problem constants ----------------
#define NTOK   131072          // H*W*B = 64*64*32
#define CDIM   512
#define NB     2048            // Nb axis = ws*ws*B
#define BATCH  32
#define SHIFTV 4

// ---------------- scratch (device globals; no allocs allowed) ----------------
__device__ float g_xw  [(size_t)NTOK * CDIM];        // LN1 + shifted window partition (tf32-rounded)
__device__ float g_qkv [(size_t)NTOK * 3 * CDIM];    // qkv activations
__device__ float g_ctx [(size_t)NTOK * CDIM];        // attention context (tf32-rounded)
__device__ float g_attn[(size_t)NTOK * CDIM];        // proj out + residual (window order)
__device__ float g_hs  [(size_t)NTOK * CDIM];        // hidden + LN2(hidden)  (fc2 residual)
__device__ float g_zln [(size_t)NTOK * CDIM];        // LN2(hidden) (tf32-rounded, fc1 input)
__device__ float g_act1[(size_t)NTOK * 4 * CDIM];    // gelu(fc1) (tf32-rounded)
// tf32-rounded weights
__device__ float g_wqkv [512 * 1536];
__device__ float g_wproj[512 * 512];
__device__ float g_wfc1 [512 * 2048];
__device__ float g_wfc2 [2048 * 512];

// ---------------- helpers ----------------
__device__ __forceinline__ float warp_sum(float v) {
#pragma unroll
    for (int o = 16; o; o >>= 1) v += __shfl_xor_sync(0xffffffffu, v, o);
    return v;
}

// round-to-nearest tf32 (low 13 mantissa bits zeroed); result is valid fp32
__device__ __forceinline__ float rnd_tf32(float x) {
    unsigned u;
    asm("cvt.rna.tf32.f32 %0, %1;" : "=r"(u) : "f"(x));
    return __uint_as_float(u);
}

__device__ __forceinline__ void mma_tf32(float (&d)[4], const unsigned (&a)[4], const unsigned (&b)[2]) {
    asm volatile(
        "mma.sync.aligned.m16n8k8.row.col.f32.tf32.tf32.f32 "
        "{%0,%1,%2,%3}, {%4,%5,%6,%7}, {%8,%9}, {%0,%1,%2,%3};"
        : "+f"(d[0]), "+f"(d[1]), "+f"(d[2]), "+f"(d[3])
        : "r"(a[0]), "r"(a[1]), "r"(a[2]), "r"(a[3]), "r"(b[0]), "r"(b[1]));
}

__device__ __forceinline__ float gelu_exact(float x) {
    return 0.5f * x * (1.0f + erff(x * 0.70710678118654752f));
}

__device__ __forceinline__ void cp_async16(unsigned smem_addr, const void* gptr) {
    asm volatile("cp.async.cg.shared.global [%0], [%1], 16;" :: "r"(smem_addr), "l"(gptr));
}
__device__ __forceinline__ void cp_commit() { asm volatile("cp.async.commit_group;"); }
__device__ __forceinline__ void cp_wait1()  { asm volatile("cp.async.wait_group 1;"); }
__device__ __forceinline__ void cp_wait0()  { asm volatile("cp.async.wait_group 0;"); }

// ---------------- K0: tf32-round weights into scratch ----------------
__global__ void round_w_kernel(const float* __restrict__ s, float* __restrict__ d) {
    int i = blockIdx.x * blockDim.x + threadIdx.x;
    float4 v = ((const float4*)s)[i];
    v.x = rnd_tf32(v.x); v.y = rnd_tf32(v.y);
    v.z = rnd_tf32(v.z); v.w = rnd_tf32(v.w);
    ((float4*)d)[i] = v;
}

// ---------------- K1: LN1 + roll(-4,-4) + window partition (tf32-rounded out) ----
__global__ void ln1_partition_kernel(const float* __restrict__ x,
                                     const float* __restrict__ g,
                                     const float* __restrict__ b,
                                     float* __restrict__ y)
{
    int warp = (blockIdx.x * blockDim.x + threadIdx.x) >> 5;
    int lane = threadIdx.x & 31;
    int r = warp;
    int win = r >> 11, n = r & 2047;
    int p = n >> 5, bb = n & 31;
    int hs = ((win >> 3) * 8 + (p >> 3) + SHIFTV) & 63;
    int ws2 = ((win & 7) * 8 + (p & 7) + SHIFTV) & 63;
    size_t src = (((size_t)(hs * 64 + ws2)) * BATCH + bb) * CDIM;

    float4 v[4];
#pragma unroll
    for (int q = 0; q < 4; q++)
        v[q] = *(const float4*)(x + src + (size_t)(q * 32 + lane) * 4);

    float s = 0.f;
#pragma unroll
    for (int q = 0; q < 4; q++) s += v[q].x + v[q].y + v[q].z + v[q].w;
    s = warp_sum(s);
    float mu = s * (1.0f / 512.0f);

    float vs = 0.f;
#pragma unroll
    for (int q = 0; q < 4; q++) {
        float a0 = v[q].x - mu, a1 = v[q].y - mu, a2 = v[q].z - mu, a3 = v[q].w - mu;
        vs += a0 * a0 + a1 * a1 + a2 * a2 + a3 * a3;
    }
    vs = warp_sum(vs);
    float rstd = rsqrtf(vs * (1.0f / 512.0f) + 1e-5f);

    size_t dst = (size_t)r * CDIM;
#pragma unroll
    for (int q = 0; q < 4; q++) {
        int c0 = (q * 32 + lane) * 4;
        float4 gv = __ldg((const float4*)(g + c0));
        float4 bv = __ldg((const float4*)(b + c0));
        float4 o;
        o.x = rnd_tf32((v[q].x - mu) * rstd * gv.x + bv.x);
        o.y = rnd_tf32((v[q].y - mu) * rstd * gv.y + bv.y);
        o.z = rnd_tf32((v[q].z - mu) * rstd * gv.z + bv.z);
        o.w = rnd_tf32((v[q].w - mu) * rstd * gv.w + bv.w);
        *(float4*)(y + dst + c0) = o;
    }
}

// ---------------- K5: window reverse + unshift + residual + LN2 ----------------
// writes: zln = tf32-rounded LN2(hidden)   (FC1 input)
//         hs  = hidden + zln               (FC2 epilogue residual)
__global__ void reverse_ln2_kernel(const float* __restrict__ x0,
                                   const float* __restrict__ attn,
                                   const float* __restrict__ g,
                                   const float* __restrict__ b,
                                   float* __restrict__ hs,
                                   float* __restrict__ zln)
{
    int warp = (blockIdx.x * blockDim.x + threadIdx.x) >> 5;
    int lane = threadIdx.x & 31;
    int t = warp;
    int simg = t >> 5, bb = t & 31;
    int h = simg >> 6, w = simg & 63;
    int hp = (h + 64 - SHIFTV) & 63, wp = (w + 64 - SHIFTV) & 63;
    size_t r = ((size_t)((hp >> 3) * 8 + (wp >> 3)) * NB +
                (size_t)(((hp & 7) * 8 + (wp & 7)) * 32 + bb)) * CDIM;
    size_t d0 = (size_t)t * CDIM;

    float4 v[4];
#pragma unroll
    for (int q = 0; q < 4; q++) {
        int c0 = (q * 32 + lane) * 4;
        float4 a = *(const float4*)(x0 + d0 + c0);
        float4 c = *(const float4*)(attn + r + c0);
        v[q].x = a.x + c.x; v[q].y = a.y + c.y; v[q].z = a.z + c.z; v[q].w = a.w + c.w;
    }

    float s = 0.f;
#pragma unroll
    for (int q = 0; q < 4; q++) s += v[q].x + v[q].y + v[q].z + v[q].w;
    s = warp_sum(s);
    float mu = s * (1.0f / 512.0f);
    float vsum = 0.f;
#pragma unroll
    for (int q = 0; q < 4; q++) {
        float a0 = v[q].x - mu, a1 = v[q].y - mu, a2 = v[q].z - mu, a3 = v[q].w - mu;
        vsum += a0 * a0 + a1 * a1 + a2 * a2 + a3 * a3;
    }
    vsum = warp_sum(vsum);
    float rstd = rsqrtf(vsum * (1.0f / 512.0f) + 1e-5f);

#pragma unroll
    for (int q = 0; q < 4; q++) {
        int c0 = (q * 32 + lane) * 4;
        float4 gv = __ldg((const float4*)(g + c0));
        float4 bv = __ldg((const float4*)(b + c0));
        float4 o;
        o.x = rnd_tf32((v[q].x - mu) * rstd * gv.x + bv.x);
        o.y = rnd_tf32((v[q].y - mu) * rstd * gv.y + bv.y);
        o.z = rnd_tf32((v[q].z - mu) * rstd * gv.z + bv.z);
        o.w = rnd_tf32((v[q].w - mu) * rstd * gv.w + bv.w);
        *(float4*)(zln + d0 + c0) = o;
        float4 hv;
        hv.x = v[q].x + o.x; hv.y = v[q].y + o.y;
        hv.z = v[q].z + o.z; hv.w = v[q].w + o.w;
        *(float4*)(hs + d0 + c0) = hv;
    }
}

// ---------------- attention: one block per (n, h); 64 threads, thread = row s ----------------
__global__ __launch_bounds__(64)
void attn_kernel(const float* __restrict__ qkv, float* __restrict__ ctx)
{
    __shared__ float ksm[64][36];
    __shared__ float vsm[64][36];
    __shared__ int   rsm[64];       // region id per sequence position (mask)
    int n = blockIdx.x, hh = blockIdx.y, s = threadIdx.x;
    size_t base = ((size_t)s * NB + n) * 1536 + hh * 96;

    float4 q[8];
#pragma unroll
    for (int d = 0; d < 8; d++) q[d] = *(const float4*)(qkv + base + d * 4);
#pragma unroll
    for (int d = 0; d < 8; d++) {
        *(float4*)&ksm[s][d * 4] = *(const float4*)(qkv + base + 32 + d * 4);
        *(float4*)&vsm[s][d * 4] = *(const float4*)(qkv + base + 64 + d * 4);
    }

    {
        int wm = n & 63;
        int hr = (wm >> 3) * 8 + (s >> 3);
        int wr = (wm & 7) * 8 + (s & 7);
        int a = (hr < 56) ? 0 : (hr < 60 ? 1 : 2);
        int c = (wr < 56) ? 0 : (wr < 60 ? 1 : 2);
        rsm[s] = a * 3 + c;
    }
    __syncthreads();

    int rs = rsm[s];

    float sc[64];
#pragma unroll
    for (int t = 0; t < 64; t++) {
        float dot = 0.f;
#pragma unroll
        for (int d = 0; d < 8; d++) {
            float4 kv = *(const float4*)&ksm[t][d * 4];
            dot += q[d].x * kv.x + q[d].y * kv.y + q[d].z * kv.z + q[d].w * kv.w;
        }
        sc[t] = (rsm[t] != rs) ? -10000.0f : dot * 0.17677669529663687f;
    }

    float mx = -1e30f;
#pragma unroll
    for (int t = 0; t < 64; t++) mx = fmaxf(mx, sc[t]);
    float sum = 0.f;
#pragma unroll
    for (int t = 0; t < 64; t++) { sc[t] = expf(sc[t] - mx); sum += sc[t]; }
    float inv = 1.0f / sum;

    float acc[32];
#pragma unroll
    for (int d = 0; d < 32; d++) acc[d] = 0.f;
#pragma unroll
    for (int t = 0; t < 64; t++) {
        float pt = sc[t];
#pragma unroll
        for (int d = 0; d < 8; d++) {
            float4 vv = *(const float4*)&vsm[t][d * 4];
            acc[d * 4 + 0] += pt * vv.x;
            acc[d * 4 + 1] += pt * vv.y;
            acc[d * 4 + 2] += pt * vv.z;
            acc[d * 4 + 3] += pt * vv.w;
        }
    }
    size_t ob = ((size_t)s * NB + n) * CDIM + hh * 32;
#pragma unroll
    for (int d = 0; d < 8; d++)
        *(float4*)(ctx + ob + d * 4) = make_float4(rnd_tf32(acc[d*4]*inv),
                                                   rnd_tf32(acc[d*4+1]*inv),
                                                   rnd_tf32(acc[d*4+2]*inv),
                                                   rnd_tf32(acc[d*4+3]*inv));
}

// ---------------- tf32 mma GEMM, cp.async double-buffered, padded smem ------
// C[M,N] = A[M,K] @ B[K,N] (+ epilogue); inputs pre-rounded to tf32 so the
// mma's native truncation == round-to-nearest semantics.
// EPI 0: +bias   1: +bias +R1   2: gelu(+bias), tf32-rounded out
// Frag-read conflict proof: A banks (36g+t)%32 = 4g+t, B banks (136t+g)%32 = 8t+g,
// both perfect 0..31 lane->bank permutations.
#define AS_STRIDE 36
#define BS_STRIDE 136
#define ATILE (128 * AS_STRIDE)          // 4608 floats
#define BTILE (32 * BS_STRIDE)           // 4352 floats
#define GEMM_SMEM ((2 * ATILE + 2 * BTILE) * 4)   // 71680 B

template<int EPI>
__global__ __launch_bounds__(256)
void gemm_tf32(const float* __restrict__ A, const float* __restrict__ B,
               const float* __restrict__ bias, float* __restrict__ C,
               const float* __restrict__ R1,
               int M, int N, int K)
{
    extern __shared__ float smem[];
    float* As = smem;                    // [2][128][AS_STRIDE]
    float* Bs = smem + 2 * ATILE;        // [2][32][BS_STRIDE]

    int tid = threadIdx.x;
    int lane = tid & 31, wid = tid >> 5;
    int wm = wid >> 1, wn = wid & 1;     // 4x2 warp grid: 32 rows x 64 cols each
    int gid = lane >> 2, tig = lane & 3;

    size_t bm0 = (size_t)blockIdx.y * 128;
    int bn0 = blockIdx.x * 128;

    // staging coordinates
    const int a_row = tid >> 3;          // + 32*l
    const int a_cc  = (tid & 7) * 4;
    const int b_row = tid >> 5;          // + 8*l
    const int b_cc  = (tid & 31) * 4;

    // smem dst addresses (buffer 0); buffer 1 adds tile bytes
    unsigned adst[4], bdst[4];
#pragma unroll
    for (int l = 0; l < 4; l++) {
        adst[l] = (unsigned)__cvta_generic_to_shared(
                      &As[(a_row + 32 * l) * AS_STRIDE + a_cc]);
        bdst[l] = (unsigned)__cvta_generic_to_shared(
                      &Bs[(b_row + 8 * l) * BS_STRIDE + b_cc]);
    }
    // gmem src base pointers (k-offset added per tile)
    const float* aptr[4];
    const float* bptr[4];
#pragma unroll
    for (int l = 0; l < 4; l++) {
        aptr[l] = A + (bm0 + a_row + 32 * l) * (size_t)K + a_cc;
        bptr[l] = B + (size_t)(b_row + 8 * l) * N + bn0 + b_cc;
    }

    float acc[2][8][4];
#pragma unroll
    for (int mt = 0; mt < 2; mt++)
#pragma unroll
        for (int nt = 0; nt < 8; nt++)
#pragma unroll
            for (int i = 0; i < 4; i++) acc[mt][nt][i] = 0.f;

    const int NT = K >> 5;

    // prologue: issue tile 0
    {
#pragma unroll
        for (int l = 0; l < 4; l++) cp_async16(adst[l], aptr[l]);
#pragma unroll
        for (int l = 0; l < 4; l++) cp_async16(bdst[l], bptr[l]);
        cp_commit();
    }

    for (int kt = 0; kt < NT; kt++) {
        bool has = (kt + 1 < NT);
        // issue tile kt+1 into the other buffer (safe: all reads of that
        // buffer finished before the barrier ending iteration kt-1)
        if (has) {
            int k0 = (kt + 1) << 5;
            unsigned aoff = ((kt + 1) & 1) ? (unsigned)(ATILE * 4) : 0u;
            unsigned boff = ((kt + 1) & 1) ? (unsigned)(BTILE * 4) : 0u;
#pragma unroll
            for (int l = 0; l < 4; l++) cp_async16(adst[l] + aoff, aptr[l] + k0);
#pragma unroll
            for (int l = 0; l < 4; l++) cp_async16(bdst[l] + boff, bptr[l] + (size_t)k0 * N);
            cp_commit();
            cp_wait1();     // group for tile kt complete
        } else {
            cp_wait0();
        }
        __syncthreads();

        const float* Ac = As + (kt & 1) * ATILE;
        const float* Bc = Bs + (kt & 1) * BTILE;

#pragma unroll
        for (int ks = 0; ks < 4; ks++) {
            unsigned a[2][4], b[8][2];
#pragma unroll
            for (int mt = 0; mt < 2; mt++) {
                int r0 = wm * 32 + mt * 16 + gid;
                a[mt][0] = __float_as_uint(Ac[r0 * AS_STRIDE + ks * 8 + tig]);
                a[mt][1] = __float_as_uint(Ac[(r0 + 8) * AS_STRIDE + ks * 8 + tig]);
                a[mt][2] = __float_as_uint(Ac[r0 * AS_STRIDE + ks * 8 + tig + 4]);
                a[mt][3] = __float_as_uint(Ac[(r0 + 8) * AS_STRIDE + ks * 8 + tig + 4]);
            }
#pragma unroll
            for (int nt = 0; nt < 8; nt++) {
                int c0 = wn * 64 + nt * 8 + gid;
                b[nt][0] = __float_as_uint(Bc[(ks * 8 + tig) * BS_STRIDE + c0]);
                b[nt][1] = __float_as_uint(Bc[(ks * 8 + tig + 4) * BS_STRIDE + c0]);
            }
#pragma unroll
            for (int mt = 0; mt < 2; mt++)
#pragma unroll
                for (int nt = 0; nt < 8; nt++)
                    mma_tf32(acc[mt][nt], a[mt], b[nt]);
        }
        __syncthreads();
    }

    // ---- epilogue ----
#pragma unroll
    for (int mt = 0; mt < 2; mt++) {
#pragma unroll
        for (int half = 0; half < 2; half++) {
            size_t row = bm0 + wm * 32 + mt * 16 + gid + half * 8;
#pragma unroll
            for (int nt = 0; nt < 8; nt++) {
                int col = bn0 + wn * 64 + nt * 8 + tig * 2;
                float2 bv = __ldg((const float2*)(bias + col));
                float v0 = acc[mt][nt][half * 2 + 0] + bv.x;
                float v1 = acc[mt][nt][half * 2 + 1] + bv.y;
                size_t idx = row * (size_t)N + col;
                if (EPI == 1) {
                    float2 r1 = *(const float2*)(R1 + idx);
                    v0 += r1.x; v1 += r1.y;
                }
                if (EPI == 2) {
                    v0 = rnd_tf32(gelu_exact(v0));
                    v1 = rnd_tf32(gelu_exact(v1));
                }
                *(float2*)(C + idx) = make_float2(v0, v1);
            }
        }
    }
}

// ---------------- launch ----------------
extern "C" void kernel_launch(void* const* d_in, const int* in_sizes, int n_in,
                              void* d_out, int out_size)
{
    const float* hid    = (const float*)d_in[0];
    const float* ln1_g  = (const float*)d_in[1];
    const float* ln1_b  = (const float*)d_in[2];
    const float* w_qkv  = (const float*)d_in[3];
    const float* b_qkv  = (const float*)d_in[4];
    const float* w_proj = (const float*)d_in[5];
    const float* b_proj = (const float*)d_in[6];
    const float* ln2_g  = (const float*)d_in[7];
    const float* ln2_b  = (const float*)d_in[8];
    const float* w_fc1  = (const float*)d_in[9];
    const float* b_fc1  = (const float*)d_in[10];
    const float* w_fc2  = (const float*)d_in[11];
    const float* b_fc2  = (const float*)d_in[12];
    float* out = (float*)d_out;

    float *xw, *qkv, *ctx, *attn, *hs, *zln, *act1;
    float *wqkv, *wproj, *wfc1, *wfc2;
    cudaGetSymbolAddress((void**)&xw,   g_xw);
    cudaGetSymbolAddress((void**)&qkv,  g_qkv);
    cudaGetSymbolAddress((void**)&ctx,  g_ctx);
    cudaGetSymbolAddress((void**)&attn, g_attn);
    cudaGetSymbolAddress((void**)&hs,   g_hs);
    cudaGetSymbolAddress((void**)&zln,  g_zln);
    cudaGetSymbolAddress((void**)&act1, g_act1);
    cudaGetSymbolAddress((void**)&wqkv, g_wqkv);
    cudaGetSymbolAddress((void**)&wproj,g_wproj);
    cudaGetSymbolAddress((void**)&wfc1, g_wfc1);
    cudaGetSymbolAddress((void**)&wfc2, g_wfc2);

    cudaFuncSetAttribute(gemm_tf32<0>, cudaFuncAttributeMaxDynamicSharedMemorySize, GEMM_SMEM);
    cudaFuncSetAttribute(gemm_tf32<1>, cudaFuncAttributeMaxDynamicSharedMemorySize, GEMM_SMEM);
    cudaFuncSetAttribute(gemm_tf32<2>, cudaFuncAttributeMaxDynamicSharedMemorySize, GEMM_SMEM);

    // 0) tf32-round weights once per replay (deterministic, ~16MB traffic)
    round_w_kernel<<<(512 * 1536) / 1024, 256>>>(w_qkv,  wqkv);
    round_w_kernel<<<(512 * 512)  / 1024, 256>>>(w_proj, wproj);
    round_w_kernel<<<(512 * 2048) / 1024, 256>>>(w_fc1,  wfc1);
    round_w_kernel<<<(2048 * 512) / 1024, 256>>>(w_fc2,  wfc2);

    // 1) LN1 + shift + partition (tf32-rounded)
    ln1_partition_kernel<<<NTOK / 8, 256>>>(hid, ln1_g, ln1_b, xw);
    // 2) QKV GEMM [131072,512]x[512,1536]
    gemm_tf32<0><<<dim3(1536 / 128, NTOK / 128), 256, GEMM_SMEM>>>(xw, wqkv, b_qkv, qkv,
                                                                   nullptr, NTOK, 1536, 512);
    // 3) windowed attention (ctx tf32-rounded)
    attn_kernel<<<dim3(NB, 16), 64>>>(qkv, ctx);
    // 4) proj GEMM + residual(xw)
    gemm_tf32<1><<<dim3(512 / 128, NTOK / 128), 256, GEMM_SMEM>>>(ctx, wproj, b_proj, attn,
                                                                  xw, NTOK, 512, 512);
    // 5) window reverse + unshift + residual + LN2  (hs = hidden + zln)
    reverse_ln2_kernel<<<NTOK / 8, 256>>>(hid, attn, ln2_g, ln2_b, hs, zln);
    // 6) FC1 + gelu (act1 tf32-rounded)
    gemm_tf32<2><<<dim3(2048 / 128, NTOK / 128), 256, GEMM_SMEM>>>(zln, wfc1, b_fc1, act1,
                                                                   nullptr, NTOK, 2048, 512);
    // 7) FC2 + bias + (hidden + zln)  -> final output
    gemm_tf32<1><<<dim3(512 / 128, NTOK / 128), 256, GEMM_SMEM>>>(act1, wfc2, b_fc2, out,
                                                                  hs, NTOK, 512, 2048);
}